// round 11
// baseline (speedup 1.0000x reference)
#include <cuda_runtime.h>
#include <cuda_bf16.h>

#define NB 8
#define NN 2048
#define NTHREADS 512
#define RPB 8                         // rows per block (same batch: 2048 % 8 == 0)
#define NWARPS (NTHREADS / 32)        // 16

struct P3 { float x, y, z; };

// Load 4 consecutive columns' coordinates (12 floats, 16B-aligned), pre-scaled.
__device__ __forceinline__ void load_cols4(const float* __restrict__ cb,
                                           int col0, float sc, P3 p[4])
{
    const float4* f = reinterpret_cast<const float4*>(cb + 3 * col0);
    float4 f0 = f[0], f1 = f[1], f2 = f[2];
    p[0] = { f0.x * sc, f0.y * sc, f0.z * sc };
    p[1] = { f0.w * sc, f1.x * sc, f1.y * sc };
    p[2] = { f1.z * sc, f1.w * sc, f2.x * sc };
    p[3] = { f2.y * sc, f2.z * sc, f2.w * sc };
}

// Masked Gaussian for 4 columns (coords pre-scaled by sqrt(log2e)/sigma):
// a = exp2(-(dx^2+dy^2+dz^2)) * m  ==  exp(-d/sigma^2) * m
__device__ __forceinline__ float4 gauss4(P3 ci, const P3 p[4], float4 m)
{
    float4 a;
    #pragma unroll
    for (int k = 0; k < 4; k++) {
        float dx = ci.x - p[k].x;
        float dy = ci.y - p[k].y;
        float dz = ci.z - p[k].z;
        float e  = __fmaf_rn(dx, -dx, __fmaf_rn(dy, -dy, -dz * dz));
        float v  = exp2f(e);
        (&a.x)[k] = v * (&m.x)[k];
    }
    return a;
}

__global__ __launch_bounds__(NTHREADS, 3) void gauss_adj_kernel(
    const float* __restrict__ coords,    // [B, N, 3]
    const float4* __restrict__ masks,    // [B, N, N] as float4
    const float* __restrict__ sigma,     // [1]
    float4* __restrict__ out)            // [B, N, N] as float4
{
    __shared__ P3    sci[RPB];           // scaled query coords for block's rows
    __shared__ float wsum[2][NWARPS];    // double-buffered cross-warp partials

    const int tid  = threadIdx.x;
    const int lane = tid & 31;
    const int wid  = tid >> 5;

    const int row0 = blockIdx.x * RPB;   // first row of this block
    const int b    = row0 >> 11;         // batch index (row0 / N)
    const float* cb = coords + (size_t)b * NN * 3;

    const float4* mptr = masks + (size_t)row0 * (NN / 4);
    float4*       optr = out   + (size_t)row0 * (NN / 4);

    // Depth-2 pipeline: rows 0 and 1 in flight before the prologue finishes.
    float4 m0 = __ldcs(mptr + tid);                 // row 0
    float4 m1 = __ldcs(mptr + (NN / 4) + tid);      // row 1

    // sqrt(log2(e)) / sigma — folds 1/sigma^2 and the exp->exp2 constant
    // into the coordinate pre-scale.
    const float s  = sigma[0];
    const float sc = __fsqrt_rn(1.4426950408889634f) / s;

    // This thread's 4 columns, resident in registers for all RPB rows.
    P3 pc[4];
    load_cols4(cb, 4 * tid, sc, pc);

    // Stage the RPB query-point coords (scaled).
    if (tid < RPB) {
        int i = (row0 + tid) & (NN - 1);
        sci[tid] = { cb[3*i] * sc, cb[3*i + 1] * sc, cb[3*i + 2] * sc };
    }
    __syncthreads();

    #pragma unroll
    for (int r = 0; r < RPB; r++) {
        // Issue row r+2's mask load before row r's compute/reduce/barrier,
        // keeping two rows of DRAM latency in flight across the barrier phase.
        float4 m2 = make_float4(0.f, 0.f, 0.f, 0.f);
        if (r + 2 < RPB)
            m2 = __ldcs(mptr + (size_t)(r + 2) * (NN / 4) + tid);

        const P3 ci = sci[r];
        float4 a = gauss4(ci, pc, m0);

        float sum = (a.x + a.y) + (a.z + a.w);

        #pragma unroll
        for (int off = 16; off > 0; off >>= 1)
            sum += __shfl_down_sync(0xffffffffu, sum, off);

        if (lane == 0) wsum[r & 1][wid] = sum;
        __syncthreads();

        float total = 0.0f;
        #pragma unroll
        for (int k = 0; k < NWARPS; k++) total += wsum[r & 1][k];

        const float inv = 1.0f / (total + 1e-8f);

        __stcs(optr + (size_t)r * (NN / 4) + tid,
               make_float4(a.x * inv, a.y * inv, a.z * inv, a.w * inv));

        m0 = m1;
        m1 = m2;
        // No trailing barrier: buffer r&1 is only rewritten at r+2, and the
        // r+1 barrier separates any straggler reads from that write.
    }
}

extern "C" void kernel_launch(void* const* d_in, const int* in_sizes, int n_in,
                              void* d_out, int out_size)
{
    const float*  coords = (const float*)d_in[0];   // [8,2048,3]
    const float4* masks  = (const float4*)d_in[1];  // [8,2048,2048]
    const float*  sigma  = (const float*)d_in[2];   // [1]
    float4*       out    = (float4*)d_out;          // [8,2048,2048]

    (void)in_sizes; (void)n_in; (void)out_size;

    dim3 grid(NB * NN / RPB);   // 2048 blocks
    dim3 block(NTHREADS);
    gauss_adj_kernel<<<grid, block>>>(coords, masks, sigma, out);
}

// round 12
// speedup vs baseline: 1.0412x; 1.0412x over previous
#include <cuda_runtime.h>
#include <cuda_bf16.h>

#define NB 8
#define NN 2048
#define NTHREADS 256
#define RPB 8                         // rows per block (same batch: 2048 % 8 == 0)
#define NWARPS (NTHREADS / 32)        // 8

struct P3 { float x, y, z; };

// Load 4 consecutive columns' coordinates (12 floats, 16B-aligned), pre-scaled.
__device__ __forceinline__ void load_cols4(const float* __restrict__ cb,
                                           int col0, float sc, P3 p[4])
{
    const float4* f = reinterpret_cast<const float4*>(cb + 3 * col0);
    float4 f0 = f[0], f1 = f[1], f2 = f[2];
    p[0] = { f0.x * sc, f0.y * sc, f0.z * sc };
    p[1] = { f0.w * sc, f1.x * sc, f1.y * sc };
    p[2] = { f1.z * sc, f1.w * sc, f2.x * sc };
    p[3] = { f2.y * sc, f2.z * sc, f2.w * sc };
}

// Masked Gaussian for 4 columns (coords pre-scaled by sqrt(log2e)/sigma):
// a = exp2(-(dx^2+dy^2+dz^2)) * m  ==  exp(-d/sigma^2) * m
__device__ __forceinline__ float4 gauss4(P3 ci, const P3 p[4], float4 m)
{
    float4 a;
    #pragma unroll
    for (int k = 0; k < 4; k++) {
        float dx = ci.x - p[k].x;
        float dy = ci.y - p[k].y;
        float dz = ci.z - p[k].z;
        float e  = __fmaf_rn(dx, -dx, __fmaf_rn(dy, -dy, -dz * dz));
        float v  = exp2f(e);
        (&a.x)[k] = v * (&m.x)[k];
    }
    return a;
}

__global__ __launch_bounds__(NTHREADS, 3) void gauss_adj_kernel(
    const float* __restrict__ coords,    // [B, N, 3]
    const float4* __restrict__ masks,    // [B, N, N] as float4
    const float* __restrict__ sigma,     // [1]
    float4* __restrict__ out)            // [B, N, N] as float4
{
    __shared__ P3    sci[RPB];           // scaled query coords for block's rows
    __shared__ float wsum[2][NWARPS];    // double-buffered cross-warp partials

    const int tid  = threadIdx.x;
    const int lane = tid & 31;
    const int wid  = tid >> 5;

    const int row0 = blockIdx.x * RPB;   // first row of this block
    const int b    = row0 >> 11;         // batch index (row0 / N)
    const float* cb = coords + (size_t)b * NN * 3;

    const float4* mptr = masks + (size_t)row0 * (NN / 4);
    float4*       optr = out   + (size_t)row0 * (NN / 4);

    // Depth-2 pipeline: rows 0 and 1 in flight before the prologue finishes.
    float4 mA0 = __ldcs(mptr + tid);
    float4 mB0 = __ldcs(mptr + tid + NTHREADS);
    float4 mA1 = __ldcs(mptr + (NN / 4) + tid);
    float4 mB1 = __ldcs(mptr + (NN / 4) + tid + NTHREADS);

    // sqrt(log2(e)) / sigma — folds 1/sigma^2 and the exp->exp2 constant
    // into the coordinate pre-scale.
    const float s  = sigma[0];
    const float sc = __fsqrt_rn(1.4426950408889634f) / s;

    // Per-thread column coordinates (scaled), resident for all RPB rows.
    P3 pA[4], pB[4];
    load_cols4(cb, 4 * tid,              sc, pA);
    load_cols4(cb, 4 * (tid + NTHREADS), sc, pB);

    // Stage the RPB query-point coords (scaled).
    if (tid < RPB) {
        int i = (row0 + tid) & (NN - 1);
        sci[tid] = { cb[3*i] * sc, cb[3*i + 1] * sc, cb[3*i + 2] * sc };
    }
    __syncthreads();

    #pragma unroll
    for (int r = 0; r < RPB; r++) {
        // Issue row r+2's mask loads before row r's compute/reduce/barrier:
        // two full rows of DRAM latency stay in flight across the barrier.
        float4 nA = make_float4(0.f, 0.f, 0.f, 0.f);
        float4 nB = nA;
        if (r + 2 < RPB) {
            const float4* mnext = mptr + (size_t)(r + 2) * (NN / 4);
            nA = __ldcs(mnext + tid);
            nB = __ldcs(mnext + tid + NTHREADS);
        }

        const P3 ci = sci[r];
        float4 aA = gauss4(ci, pA, mA0);
        float4 aB = gauss4(ci, pB, mB0);

        float sum = (aA.x + aA.y) + (aA.z + aA.w)
                  + (aB.x + aB.y) + (aB.z + aB.w);

        #pragma unroll
        for (int off = 16; off > 0; off >>= 1)
            sum += __shfl_down_sync(0xffffffffu, sum, off);

        if (lane == 0) wsum[r & 1][wid] = sum;
        __syncthreads();

        float total = 0.0f;
        #pragma unroll
        for (int k = 0; k < NWARPS; k++) total += wsum[r & 1][k];

        const float inv = 1.0f / (total + 1e-8f);

        float4* orow = optr + (size_t)r * (NN / 4);
        __stcs(orow + tid,            make_float4(aA.x*inv, aA.y*inv, aA.z*inv, aA.w*inv));
        __stcs(orow + tid + NTHREADS, make_float4(aB.x*inv, aB.y*inv, aB.z*inv, aB.w*inv));

        mA0 = mA1; mB0 = mB1;
        mA1 = nA;  mB1 = nB;
        // No trailing barrier: buffer r&1 is only rewritten at r+2, and the
        // r+1 barrier separates any straggler reads from that write.
    }
}

extern "C" void kernel_launch(void* const* d_in, const int* in_sizes, int n_in,
                              void* d_out, int out_size)
{
    const float*  coords = (const float*)d_in[0];   // [8,2048,3]
    const float4* masks  = (const float4*)d_in[1];  // [8,2048,2048]
    const float*  sigma  = (const float*)d_in[2];   // [1]
    float4*       out    = (float4*)d_out;          // [8,2048,2048]

    (void)in_sizes; (void)n_in; (void)out_size;

    dim3 grid(NB * NN / RPB);   // 2048 blocks
    dim3 block(NTHREADS);
    gauss_adj_kernel<<<grid, block>>>(coords, masks, sigma, out);
}